// round 13
// baseline (speedup 1.0000x reference)
/*
 R12 theory.
 R11 = 355us. Remaining cost model: P-GEMM writes 134MB/conv to DRAM and
 contract reads it back (134MB/conv) -> ~536MB total P round-trip ~ 90-100us,
 plus both kernels' latency. Everything else (GEMM1 ~25us, contract MMA+atomics,
 sort ~20us, mlp1 ~10us) is smaller.
 Change this round: CHUNKED P WITH L2 RESIDENCY. Instead of materializing all
 4096 nodes' P then contracting, interleave per 1024-node chunk:
    pgemm(chunk c) -> contract(chunk c), c = 0..3, per conv,
 with P written to a small reused ring buffer g_Pc[1024*16384] fp16 = 32MB.
 The chunk fits in the 126MB L2, so contract's P reads hit L2 (~234cyc/
 6300B/cyc path) instead of DRAM, and the same 32MB region is re-dirtied each
 chunk so steady-state DRAM writeback is bounded and off the critical path.
 Arithmetic is bit-identical to R11 -> rel_err should stay exactly 4.05e-4.
 Cost: 12 extra dependent graph launches (~1-2us each serialization).
 Predicted: dur 355 -> ~285-310us. If the delta is much smaller, the gap is
 launch-gap/latency bound, not bandwidth bound -> next round pipeline the
 GEMMs with cp.async and merge pgemm+contract into one fused kernel.
*/
#include <cuda_runtime.h>
#include <cuda_fp16.h>
#include <cstdint>
#include <cstddef>

#define N_NODES 4096
#define N_EDGES 65536
#define L_DIM   64
#define K_DIM   256
#define ED_DIM  6
#define P_COLS  (K_DIM*L_DIM)   /* 16384 */
#define CHUNK   1024
#define N_CHUNKS (N_NODES/CHUNK)

/* device-global scratch (no runtime allocation allowed) */
__device__ __align__(16) __half g_h1[(size_t)N_EDGES*K_DIM];    /* 32 MB */
__device__ __align__(16) __half g_h2h[(size_t)N_EDGES*K_DIM];   /* 32 MB gelu(mlp2) fp16 */
__device__ __align__(16) __half g_W2h[K_DIM*K_DIM];
__device__ __align__(16) __half g_T2h[(size_t)L_DIM*P_COLS];    /* W3 permuted [i][k*64+o] */
__device__ __align__(16) __half g_Pc[(size_t)CHUNK*P_COLS];     /* 32 MB chunk P, L2-resident */
__device__ __align__(16) __half g_xh[N_NODES*L_DIM];
__device__ __align__(16) float  g_Q[N_NODES*L_DIM];
__device__ __align__(16) float  g_t1[N_NODES*L_DIM];
__device__ __align__(16) float  g_x1[N_NODES*L_DIM];
__device__ int g_cnt[N_NODES];
__device__ int g_off[N_NODES+1];
__device__ int g_cur[N_NODES];
__device__ int g_order[N_EDGES];

__device__ __forceinline__ float gelu_f(float x){
    return 0.5f*x*(1.0f+erff(x*0.70710678118654752440f));
}

/* mma helpers */
__device__ __forceinline__ void ldm_x4(uint32_t* r, const void* p){
    uint32_t a = (uint32_t)__cvta_generic_to_shared(p);
    asm volatile("ldmatrix.sync.aligned.m8n8.x4.shared.b16 {%0,%1,%2,%3},[%4];"
                 : "=r"(r[0]),"=r"(r[1]),"=r"(r[2]),"=r"(r[3]) : "r"(a));
}
__device__ __forceinline__ void ldm_x4_t(uint32_t* r, const void* p){
    uint32_t a = (uint32_t)__cvta_generic_to_shared(p);
    asm volatile("ldmatrix.sync.aligned.m8n8.x4.trans.shared.b16 {%0,%1,%2,%3},[%4];"
                 : "=r"(r[0]),"=r"(r[1]),"=r"(r[2]),"=r"(r[3]) : "r"(a));
}
__device__ __forceinline__ void ldm_x2_t(uint32_t* r, const void* p){
    uint32_t a = (uint32_t)__cvta_generic_to_shared(p);
    asm volatile("ldmatrix.sync.aligned.m8n8.x2.trans.shared.b16 {%0,%1},[%2];"
                 : "=r"(r[0]),"=r"(r[1]) : "r"(a));
}
__device__ __forceinline__ void mma16816(float* d, const uint32_t* a, const uint32_t* b){
    asm volatile("mma.sync.aligned.m16n8k16.row.col.f32.f16.f16.f32 "
                 "{%0,%1,%2,%3},{%4,%5,%6,%7},{%8,%9},{%0,%1,%2,%3};"
                 : "+f"(d[0]),"+f"(d[1]),"+f"(d[2]),"+f"(d[3])
                 : "r"(a[0]),"r"(a[1]),"r"(a[2]),"r"(a[3]),"r"(b[0]),"r"(b[1]));
}

/* counting sort of edges by src */
__global__ void k_zero(){
    int i = blockIdx.x*blockDim.x + threadIdx.x;
    if (i < N_NODES) g_cnt[i] = 0;
}
__global__ void k_hist(const int* __restrict__ ei){
    int e = blockIdx.x*blockDim.x + threadIdx.x;
    if (e < N_EDGES) atomicAdd(&g_cnt[ei[e]], 1);
}
__global__ void k_scan(){   /* 1024 threads, 4 elems each */
    int t = threadIdx.x;
    int b = t*4;
    int v0=g_cnt[b], v1=g_cnt[b+1], v2=g_cnt[b+2], v3=g_cnt[b+3];
    int s1=v0+v1, s2=s1+v2, s3=s2+v3;
    int lane=t&31, warp=t>>5;
    int x=s3;
    #pragma unroll
    for(int d=1;d<32;d<<=1){ int y=__shfl_up_sync(0xffffffffu,x,d); if(lane>=d) x+=y; }
    __shared__ int ws[32];
    if(lane==31) ws[warp]=x;
    __syncthreads();
    if(warp==0){
        int y=ws[lane];
        #pragma unroll
        for(int d=1;d<32;d<<=1){ int z=__shfl_up_sync(0xffffffffu,y,d); if(lane>=d) y+=z; }
        ws[lane]=y;
    }
    __syncthreads();
    int wex = (warp==0)?0:ws[warp-1];
    int ex = wex + (x - s3);
    g_off[b]=ex;        g_cur[b]=ex;
    g_off[b+1]=ex+v0;   g_cur[b+1]=ex+v0;
    g_off[b+2]=ex+s1;   g_cur[b+2]=ex+s1;
    g_off[b+3]=ex+s2;   g_cur[b+3]=ex+s2;
    if(t==1023) g_off[N_NODES]=wex+x;
}
__global__ void k_scatter(const int* __restrict__ ei){
    int e = blockIdx.x*blockDim.x + threadIdx.x;
    if (e < N_EDGES){
        int pos = atomicAdd(&g_cur[ei[e]], 1);
        g_order[pos] = e;
    }
}

/* weight conversions */
__global__ void k_w2h(const float* __restrict__ W2){
    int i = blockIdx.x*blockDim.x + threadIdx.x;
    if (i < K_DIM*K_DIM) g_W2h[i] = __float2half(W2[i]);
}
/* T2h[i][k*64+o] = W3[k][i*64+o] */
__global__ void k_t2h(const float* __restrict__ W3){
    int idx = blockIdx.x*blockDim.x + threadIdx.x;
    if (idx >= K_DIM*L_DIM*L_DIM) return;
    int k = idx >> 12;
    int i = (idx >> 6) & 63;
    int o = idx & 63;
    g_T2h[(size_t)i*P_COLS + k*L_DIM + o] = __float2half(W3[idx]);
}

/* edge MLP layer 1: h1 = gelu(ea@W1 + b1), fp16 out */
__global__ void __launch_bounds__(256) k_mlp1(const float* __restrict__ ea,
                                              const float* __restrict__ W1,
                                              const float* __restrict__ b1){
    __shared__ float W1s[ED_DIM*K_DIM];
    __shared__ float eas[16][ED_DIM];
    int t = threadIdx.x;
    for (int j=t; j<ED_DIM*K_DIM; j+=256) W1s[j] = W1[j];
    int e0 = blockIdx.x*16;
    if (t < 16*ED_DIM) eas[t/ED_DIM][t%ED_DIM] = ea[e0*ED_DIM + t];
    float bb = b1[t];
    __syncthreads();
    #pragma unroll
    for (int le=0; le<16; le++){
        float s = bb;
        #pragma unroll
        for (int d=0; d<ED_DIM; d++) s += eas[le][d]*W1s[d*K_DIM + t];
        g_h1[(size_t)(e0+le)*K_DIM + t] = __float2half(gelu_f(s));
    }
}

/* fp16 MMA GEMM, 128x128 tile, 8 warps (4x2), warp 32x64, fp16 output.
   EPI 0: g_h2h = gelu(g_h1 @ g_W2h + b2)   KT=256, NC=256,  m0=0
   EPI 1: g_Pc  = g_xh[m0..] @ g_T2h        KT=64,  NC=16384 (chunk-local C) */
template<int EPI, int KT, int NC>
__global__ void __launch_bounds__(256) k_gemm(const float* __restrict__ b2, int m0){
    __shared__ __align__(16) __half As[128][40];
    __shared__ __align__(16) __half Bs[32][136];
    const __half* A = (EPI==0) ? (const __half*)g_h1 : (const __half*)g_xh;
    const __half* B = (EPI==0) ? (const __half*)g_W2h : (const __half*)g_T2h;
    __half*       C = (EPI==0) ? g_h2h : g_Pc;
    int bm = blockIdx.x, bn = blockIdx.y;
    int t = threadIdx.x, lane = t&31, wid = t>>5;
    int wm = wid & 3, wn = wid >> 2;
    float acc[2][8][4];
    #pragma unroll
    for (int mi=0;mi<2;mi++)
        #pragma unroll
        for (int nj=0;nj<8;nj++){
            acc[mi][nj][0]=0.f; acc[mi][nj][1]=0.f; acc[mi][nj][2]=0.f; acc[mi][nj][3]=0.f;
        }

    for (int kt=0; kt<KT/32; kt++){
        #pragma unroll
        for (int p=0;p<2;p++){
            int idx=t+p*256;
            int r=idx>>2, c=(idx&3)*8;
            *(uint4*)(&As[r][c]) = *(const uint4*)(A + (size_t)(m0 + bm*128+r)*KT + kt*32 + c);
        }
        #pragma unroll
        for (int p=0;p<2;p++){
            int idx=t+p*256;
            int r=idx>>4, c=(idx&15)*8;
            *(uint4*)(&Bs[r][c]) = *(const uint4*)(B + (size_t)(kt*32+r)*NC + bn*128 + c);
        }
        __syncthreads();
        #pragma unroll
        for (int k16=0;k16<2;k16++){
            uint32_t af[2][4];
            #pragma unroll
            for (int mi=0;mi<2;mi++)
                ldm_x4(af[mi], &As[wm*32 + mi*16 + (lane&15)][k16*16 + (lane>>4)*8]);
            uint32_t bf[8][2];
            #pragma unroll
            for (int np=0;np<4;np++){
                uint32_t r4[4];
                ldm_x4_t(r4, &Bs[k16*16 + ((lane>>3)&1)*8 + (lane&7)]
                               [wn*64 + np*16 + (lane>>4)*8]);
                bf[np*2  ][0]=r4[0]; bf[np*2  ][1]=r4[1];
                bf[np*2+1][0]=r4[2]; bf[np*2+1][1]=r4[3];
            }
            #pragma unroll
            for (int mi=0;mi<2;mi++)
                #pragma unroll
                for (int nj=0;nj<8;nj++)
                    mma16816(acc[mi][nj], af[mi], bf[nj]);
        }
        __syncthreads();
    }
    int row0 = bm*128 + wm*32 + (lane>>2);   /* chunk-local for EPI1 (m0=0 for EPI0) */
    int col0 = bn*128 + wn*64 + (lane&3)*2;
    #pragma unroll
    for (int mi=0;mi<2;mi++){
        #pragma unroll
        for (int nj=0;nj<8;nj++){
            int r = row0 + mi*16, c = col0 + nj*8;
            float v0=acc[mi][nj][0], v1=acc[mi][nj][1], v2=acc[mi][nj][2], v3=acc[mi][nj][3];
            if (EPI==0){
                float bc0=b2[c], bc1=b2[c+1];
                v0=gelu_f(v0+bc0); v1=gelu_f(v1+bc1);
                v2=gelu_f(v2+bc0); v3=gelu_f(v3+bc1);
            }
            *(__half2*)(C + (size_t)r*NC + c)     = __floats2half2_rn(v0, v1);
            *(__half2*)(C + (size_t)(r+8)*NC + c) = __floats2half2_rn(v2, v3);
        }
    }
}

/* per-conv prep: xh = half(x); R = x@Wroot + bias; Q = x@b3r.
   conv==0: x = nodes (ext), R -> g_t1 ; conv==1: x = g_x1, R -> out (ext) */
__global__ void k_prep(int conv, const float* __restrict__ x_ext,
                       const float* __restrict__ Wr, const float* __restrict__ bias,
                       const float* __restrict__ b3, float* __restrict__ R_ext){
    __shared__ float xs[L_DIM];
    int n = blockIdx.x, o = threadIdx.x;
    const float* x = (conv==0) ? x_ext : g_x1;
    float* R = (conv==0) ? g_t1 : R_ext;
    xs[o] = x[n*L_DIM + o];
    __syncthreads();
    g_xh[n*L_DIM + o] = __float2half(xs[o]);
    float r = bias[o], q = 0.f;
    #pragma unroll
    for (int i=0;i<L_DIM;i++){
        float xv = xs[i];
        r += xv*Wr[i*L_DIM + o];
        q += xv*b3[i*L_DIM + o];
    }
    R[n*L_DIM + o] = r;
    g_Q[n*L_DIM + o] = q;
}

/* Tensor-core contraction for one chunk: block b handles node n = n0+b, reading
   its P row from the chunk buffer g_Pc[b]. msg[16,64] = h2[16,256] @ P[256,64]
   via m16n8k16 (8 warps = 8 n-slices), then atomicAdd(msg + Q) into dst rows. */
#define PS_PITCH 72
#define HS_PITCH 264
__global__ void __launch_bounds__(256) k_contract(int conv, int n0,
                                                  const int* __restrict__ ei,
                                                  float* __restrict__ out_ext){
    extern __shared__ __align__(16) __half smh[];
    __half* Ps = smh;                       /* 256*72 halfs */
    __half* hs = smh + 256*PS_PITCH;        /* 16*264 halfs */
    float*  Qs = (float*)(hs + 16*HS_PITCH);/* 64 floats */
    float* target = (conv==0) ? g_t1 : out_ext;

    int ln = blockIdx.x;          /* chunk-local node */
    int n = n0 + ln;              /* global node */
    int beg = g_off[n], end = g_off[n+1];
    if (beg == end) return;
    int t = threadIdx.x, lane = t&31, wn = t>>5;

    /* stage P row (32KB fp16) with pitch-72 rows */
    {
        const uint4* src = (const uint4*)(g_Pc + (size_t)ln*P_COLS);
        #pragma unroll
        for (int i=0;i<8;i++){
            int j = t + i*256;             /* 8-half chunk id, 0..2047 */
            int k = j>>3, o = (j&7)*8;
            *(uint4*)(Ps + k*PS_PITCH + o) = src[j];
        }
    }
    if (t < 64) Qs[t] = g_Q[n*L_DIM + t];

    for (int gb = beg; gb < end; gb += 16){
        int ne = min(16, end - gb);
        __syncthreads();   /* Ps/Qs ready (first iter); hs consumed (later iters) */
        /* stage h2 rows for this edge group, zero-pad missing rows */
        #pragma unroll
        for (int i=0;i<2;i++){
            int j = t + i*256;             /* 0..511 ; 32 chunks per edge row */
            int le = j>>5, c8 = j&31;
            uint4 v;
            if (le < ne){
                int e = g_order[gb+le];
                v = ((const uint4*)(g_h2h + (size_t)e*K_DIM))[c8];
            } else {
                v.x=0u; v.y=0u; v.z=0u; v.w=0u;
            }
            *(uint4*)(hs + le*HS_PITCH + c8*8) = v;
        }
        __syncthreads();

        float acc[4]; acc[0]=0.f; acc[1]=0.f; acc[2]=0.f; acc[3]=0.f;
        #pragma unroll
        for (int ks=0; ks<16; ks++){
            uint32_t af[4];
            ldm_x4(af, hs + (lane&15)*HS_PITCH + ks*16 + (lane>>4)*8);
            uint32_t bf[2];
            ldm_x2_t(bf, Ps + (ks*16 + (lane&15))*PS_PITCH + wn*8);
            mma16816(acc, af, bf);
        }

        int r0 = lane>>2;
        int c0 = wn*8 + (lane&3)*2;
        float q0 = Qs[c0], q1 = Qs[c0+1];
        if (r0 < ne){
            int e = g_order[gb+r0];
            int dst = ei[N_EDGES + e];
            float* tg = target + (size_t)dst*L_DIM + c0;
            atomicAdd(tg,   acc[0]+q0);
            atomicAdd(tg+1, acc[1]+q1);
        }
        if (r0+8 < ne){
            int e = g_order[gb+r0+8];
            int dst = ei[N_EDGES + e];
            float* tg = target + (size_t)dst*L_DIM + c0;
            atomicAdd(tg,   acc[2]+q0);
            atomicAdd(tg+1, acc[3]+q1);
        }
    }
}

__global__ void k_gelu_mid(){
    int i = blockIdx.x*blockDim.x + threadIdx.x;
    if (i < N_NODES*L_DIM) g_x1[i] = gelu_f(g_t1[i]);
}

extern "C" void kernel_launch(void* const* d_in, const int* in_sizes, int n_in,
                              void* d_out, int out_size){
    const float* nodes = (const float*)d_in[0];
    const int*   ei    = (const int*)  d_in[1];
    const float* ea    = (const float*)d_in[2];
    const float* W1    = (const float*)d_in[3];
    const float* b1    = (const float*)d_in[4];
    const float* W2    = (const float*)d_in[5];
    const float* b2    = (const float*)d_in[6];
    const float* W3    = (const float*)d_in[7];
    const float* b3    = (const float*)d_in[8];
    const float* Wr    = (const float*)d_in[9];
    const float* bias  = (const float*)d_in[10];
    float* out = (float*)d_out;
    (void)in_sizes; (void)n_in; (void)out_size;

    const int SMEM_CONTRACT = (256*PS_PITCH + 16*HS_PITCH)*2 + 64*4 + 16; /* ~45.6 KB */
    cudaFuncSetAttribute(k_contract, cudaFuncAttributeMaxDynamicSharedMemorySize, SMEM_CONTRACT);

    /* sort edges by src */
    k_zero<<<16,256>>>();
    k_hist<<<256,256>>>(ei);
    k_scan<<<1,1024>>>();
    k_scatter<<<256,256>>>(ei);

    /* weight converts */
    k_w2h<<<256,256>>>(W2);
    k_t2h<<<4096,256>>>(W3);

    /* edge MLP (once; reused across both convs) */
    k_mlp1<<<N_EDGES/16,256>>>(ea, W1, b1);
    k_gemm<0,K_DIM,K_DIM><<<dim3(N_EDGES/128, K_DIM/128), 256>>>(b2, 0);

    /* conv 1: chunked P (L2-resident ring buffer) */
    k_prep<<<N_NODES,L_DIM>>>(0, nodes, Wr, bias, b3, out);
    for (int c = 0; c < N_CHUNKS; c++){
        k_gemm<1,L_DIM,P_COLS><<<dim3(CHUNK/128, P_COLS/128), 256>>>(b2, c*CHUNK);
        k_contract<<<CHUNK,256,SMEM_CONTRACT>>>(0, c*CHUNK, ei, out);
    }
    k_gelu_mid<<<(N_NODES*L_DIM)/256,256>>>();

    /* conv 2 */
    k_prep<<<N_NODES,L_DIM>>>(1, nodes, Wr, bias, b3, out);
    for (int c = 0; c < N_CHUNKS; c++){
        k_gemm<1,L_DIM,P_COLS><<<dim3(CHUNK/128, P_COLS/128), 256>>>(b2, c*CHUNK);
        k_contract<<<CHUNK,256,SMEM_CONTRACT>>>(1, c*CHUNK, ei, out);
    }
}

// round 14
// speedup vs baseline: 1.0912x; 1.0912x over previous
/*
 R14 theory.
 Revert to R11 structure (355us). FLOP audit says the fp16 MMA GEMMs are now
 the biggest block: gemm1 8.6GF + 2x pgemm 17.2GF = 26GF; the current k_gemm
 has NO pipelining (sync LDG -> sync -> MMA per 32-k tile, 2 syncthreads/iter)
 so it likely achieves only ~100-150 TF -> ~150-180us of the 355.
 Changes:
  1. cp.async (LDGSTS) double-buffered k_gemm: overlap next tile's global
     loads with current tile's MMA; 1 syncthreads/iter instead of 2.
     Predicted GEMM time roughly halves (-60..80us).
  2. Remove k_gelu_mid: gelu folded into k_prep for conv2 (reads t1, applies
     gelu inline). Kills one launch + 2MB round trip, removes g_x1.
  3. Merge k_w2h + k_t2h into one k_wcvt launch.
  4. Contract kernel identical to R11 (proven, 4.05e-4).
 Arithmetic otherwise identical -> rel_err should stay ~4.05e-4.
 Predicted: dur 355 -> ~290-310us. If not, the residual is launch-latency /
 contract-bound -> next round fuse mlp1 into gemm1 and repack the pgemm
 epilogue (STG.32 -> STG.128 via smem) and consider tcgen05.
*/
#include <cuda_runtime.h>
#include <cuda_fp16.h>
#include <cstdint>
#include <cstddef>

#define N_NODES 4096
#define N_EDGES 65536
#define L_DIM   64
#define K_DIM   256
#define ED_DIM  6
#define P_COLS  (K_DIM*L_DIM)   /* 16384 */

/* device-global scratch (no runtime allocation allowed) */
__device__ __align__(16) __half g_h1[(size_t)N_EDGES*K_DIM];    /* 32 MB */
__device__ __align__(16) __half g_h2h[(size_t)N_EDGES*K_DIM];   /* 32 MB */
__device__ __align__(16) __half g_W2h[K_DIM*K_DIM];
__device__ __align__(16) __half g_T2h[(size_t)L_DIM*P_COLS];    /* W3 permuted [i][k*64+o] */
__device__ __align__(16) __half g_Ph[(size_t)N_NODES*P_COLS];   /* 134 MB */
__device__ __align__(16) __half g_xh[N_NODES*L_DIM];
__device__ __align__(16) float  g_Q[N_NODES*L_DIM];
__device__ __align__(16) float  g_t1[N_NODES*L_DIM];
__device__ int g_cnt[N_NODES];
__device__ int g_off[N_NODES+1];
__device__ int g_cur[N_NODES];
__device__ int g_order[N_EDGES];

__device__ __forceinline__ float gelu_f(float x){
    return 0.5f*x*(1.0f+erff(x*0.70710678118654752440f));
}

/* mma + cp.async helpers */
__device__ __forceinline__ void ldm_x4(uint32_t* r, const void* p){
    uint32_t a = (uint32_t)__cvta_generic_to_shared(p);
    asm volatile("ldmatrix.sync.aligned.m8n8.x4.shared.b16 {%0,%1,%2,%3},[%4];"
                 : "=r"(r[0]),"=r"(r[1]),"=r"(r[2]),"=r"(r[3]) : "r"(a));
}
__device__ __forceinline__ void ldm_x4_t(uint32_t* r, const void* p){
    uint32_t a = (uint32_t)__cvta_generic_to_shared(p);
    asm volatile("ldmatrix.sync.aligned.m8n8.x4.trans.shared.b16 {%0,%1,%2,%3},[%4];"
                 : "=r"(r[0]),"=r"(r[1]),"=r"(r[2]),"=r"(r[3]) : "r"(a));
}
__device__ __forceinline__ void ldm_x2_t(uint32_t* r, const void* p){
    uint32_t a = (uint32_t)__cvta_generic_to_shared(p);
    asm volatile("ldmatrix.sync.aligned.m8n8.x2.trans.shared.b16 {%0,%1},[%2];"
                 : "=r"(r[0]),"=r"(r[1]) : "r"(a));
}
__device__ __forceinline__ void mma16816(float* d, const uint32_t* a, const uint32_t* b){
    asm volatile("mma.sync.aligned.m16n8k16.row.col.f32.f16.f16.f32 "
                 "{%0,%1,%2,%3},{%4,%5,%6,%7},{%8,%9},{%0,%1,%2,%3};"
                 : "+f"(d[0]),"+f"(d[1]),"+f"(d[2]),"+f"(d[3])
                 : "r"(a[0]),"r"(a[1]),"r"(a[2]),"r"(a[3]),"r"(b[0]),"r"(b[1]));
}
__device__ __forceinline__ void cp16(void* s, const void* g){
    uint32_t a = (uint32_t)__cvta_generic_to_shared(s);
    asm volatile("cp.async.ca.shared.global [%0],[%1],16;" :: "r"(a),"l"(g));
}
__device__ __forceinline__ void cp_commit(){ asm volatile("cp.async.commit_group;"); }
__device__ __forceinline__ void cp_wait0(){ asm volatile("cp.async.wait_group 0;"); }

/* counting sort of edges by src */
__global__ void k_zero(){
    int i = blockIdx.x*blockDim.x + threadIdx.x;
    if (i < N_NODES) g_cnt[i] = 0;
}
__global__ void k_hist(const int* __restrict__ ei){
    int e = blockIdx.x*blockDim.x + threadIdx.x;
    if (e < N_EDGES) atomicAdd(&g_cnt[ei[e]], 1);
}
__global__ void k_scan(){   /* 1024 threads, 4 elems each */
    int t = threadIdx.x;
    int b = t*4;
    int v0=g_cnt[b], v1=g_cnt[b+1], v2=g_cnt[b+2], v3=g_cnt[b+3];
    int s1=v0+v1, s2=s1+v2, s3=s2+v3;
    int lane=t&31, warp=t>>5;
    int x=s3;
    #pragma unroll
    for(int d=1;d<32;d<<=1){ int y=__shfl_up_sync(0xffffffffu,x,d); if(lane>=d) x+=y; }
    __shared__ int ws[32];
    if(lane==31) ws[warp]=x;
    __syncthreads();
    if(warp==0){
        int y=ws[lane];
        #pragma unroll
        for(int d=1;d<32;d<<=1){ int z=__shfl_up_sync(0xffffffffu,y,d); if(lane>=d) y+=z; }
        ws[lane]=y;
    }
    __syncthreads();
    int wex = (warp==0)?0:ws[warp-1];
    int ex = wex + (x - s3);
    g_off[b]=ex;        g_cur[b]=ex;
    g_off[b+1]=ex+v0;   g_cur[b+1]=ex+v0;
    g_off[b+2]=ex+s1;   g_cur[b+2]=ex+s1;
    g_off[b+3]=ex+s2;   g_cur[b+3]=ex+s2;
    if(t==1023) g_off[N_NODES]=wex+x;
}
__global__ void k_scatter(const int* __restrict__ ei){
    int e = blockIdx.x*blockDim.x + threadIdx.x;
    if (e < N_EDGES){
        int pos = atomicAdd(&g_cur[ei[e]], 1);
        g_order[pos] = e;
    }
}

/* weight conversions (merged): W2 -> fp16, W3 -> permuted fp16 */
__global__ void k_wcvt(const float* __restrict__ W2, const float* __restrict__ W3){
    int idx = blockIdx.x*blockDim.x + threadIdx.x;
    if (idx < K_DIM*K_DIM) g_W2h[idx] = __float2half(W2[idx]);
    if (idx < K_DIM*L_DIM*L_DIM){
        int k = idx >> 12;
        int i = (idx >> 6) & 63;
        int o = idx & 63;
        g_T2h[(size_t)i*P_COLS + k*L_DIM + o] = __float2half(W3[idx]);
    }
}

/* edge MLP layer 1: h1 = gelu(ea@W1 + b1), fp16 out */
__global__ void __launch_bounds__(256) k_mlp1(const float* __restrict__ ea,
                                              const float* __restrict__ W1,
                                              const float* __restrict__ b1){
    __shared__ float W1s[ED_DIM*K_DIM];
    __shared__ float eas[16][ED_DIM];
    int t = threadIdx.x;
    for (int j=t; j<ED_DIM*K_DIM; j+=256) W1s[j] = W1[j];
    int e0 = blockIdx.x*16;
    if (t < 16*ED_DIM) eas[t/ED_DIM][t%ED_DIM] = ea[e0*ED_DIM + t];
    float bb = b1[t];
    __syncthreads();
    #pragma unroll
    for (int le=0; le<16; le++){
        float s = bb;
        #pragma unroll
        for (int d=0; d<ED_DIM; d++) s += eas[le][d]*W1s[d*K_DIM + t];
        g_h1[(size_t)(e0+le)*K_DIM + t] = __float2half(gelu_f(s));
    }
}

/* fp16 MMA GEMM, 128x128 tile, 8 warps (4x2), warp 32x64, fp16 output,
   cp.async double-buffered.
   EPI 0: g_h2h = gelu(g_h1 @ g_W2h + b2)   KT=256, NC=256
   EPI 1: g_Ph  = g_xh @ g_T2h              KT=64,  NC=16384 */
template<int EPI, int KT, int NC>
__global__ void __launch_bounds__(256) k_gemm(const float* __restrict__ b2){
    __shared__ __align__(16) __half As[2][128][40];
    __shared__ __align__(16) __half Bs[2][32][136];
    const __half* A = (EPI==0) ? (const __half*)g_h1 : (const __half*)g_xh;
    const __half* B = (EPI==0) ? (const __half*)g_W2h : (const __half*)g_T2h;
    __half*       C = (EPI==0) ? g_h2h : g_Ph;
    int bm = blockIdx.x, bn = blockIdx.y;
    int t = threadIdx.x, lane = t&31, wid = t>>5;
    int wm = wid & 3, wn = wid >> 2;

    /* per-thread load coords (constant across iters) */
    int ar = (t<<1)>>2 >> 1, dummy=0; (void)dummy;
    int a_r0 = (t + 0*256)>>2,   a_c0 = ((t + 0*256)&3)*8;
    int a_r1 = (t + 1*256)>>2,   a_c1 = ((t + 1*256)&3)*8;
    int b_r0 = (t + 0*256)>>4,   b_c0 = ((t + 0*256)&15)*8;
    int b_r1 = (t + 1*256)>>4,   b_c1 = ((t + 1*256)&15)*8;
    (void)ar;

    float acc[2][8][4];
    #pragma unroll
    for (int mi=0;mi<2;mi++)
        #pragma unroll
        for (int nj=0;nj<8;nj++){
            acc[mi][nj][0]=0.f; acc[mi][nj][1]=0.f; acc[mi][nj][2]=0.f; acc[mi][nj][3]=0.f;
        }

    /* prologue: stage 0 loads */
    {
        cp16(&As[0][a_r0][a_c0], A + (size_t)(bm*128+a_r0)*KT + a_c0);
        cp16(&As[0][a_r1][a_c1], A + (size_t)(bm*128+a_r1)*KT + a_c1);
        cp16(&Bs[0][b_r0][b_c0], B + (size_t)b_r0*NC + bn*128 + b_c0);
        cp16(&Bs[0][b_r1][b_c1], B + (size_t)b_r1*NC + bn*128 + b_c1);
        cp_commit();
    }

    const int NKT = KT/32;
    for (int kt=0; kt<NKT; kt++){
        cp_wait0();
        __syncthreads();
        if (kt+1 < NKT){
            int st = (kt+1)&1;
            cp16(&As[st][a_r0][a_c0], A + (size_t)(bm*128+a_r0)*KT + (kt+1)*32 + a_c0);
            cp16(&As[st][a_r1][a_c1], A + (size_t)(bm*128+a_r1)*KT + (kt+1)*32 + a_c1);
            cp16(&Bs[st][b_r0][b_c0], B + (size_t)((kt+1)*32+b_r0)*NC + bn*128 + b_c0);
            cp16(&Bs[st][b_r1][b_c1], B + (size_t)((kt+1)*32+b_r1)*NC + bn*128 + b_c1);
            cp_commit();
        }
        int cs = kt&1;
        #pragma unroll
        for (int k16=0;k16<2;k16++){
            uint32_t af[2][4];
            #pragma unroll
            for (int mi=0;mi<2;mi++)
                ldm_x4(af[mi], &As[cs][wm*32 + mi*16 + (lane&15)][k16*16 + (lane>>4)*8]);
            uint32_t bf[8][2];
            #pragma unroll
            for (int np=0;np<4;np++){
                uint32_t r4[4];
                ldm_x4_t(r4, &Bs[cs][k16*16 + ((lane>>3)&1)*8 + (lane&7)]
                               [wn*64 + np*16 + (lane>>4)*8]);
                bf[np*2  ][0]=r4[0]; bf[np*2  ][1]=r4[1];
                bf[np*2+1][0]=r4[2]; bf[np*2+1][1]=r4[3];
            }
            #pragma unroll
            for (int mi=0;mi<2;mi++)
                #pragma unroll
                for (int nj=0;nj<8;nj++)
                    mma16816(acc[mi][nj], af[mi], bf[nj]);
        }
    }
    int row0 = bm*128 + wm*32 + (lane>>2);
    int col0 = bn*128 + wn*64 + (lane&3)*2;
    #pragma unroll
    for (int mi=0;mi<2;mi++){
        #pragma unroll
        for (int nj=0;nj<8;nj++){
            int r = row0 + mi*16, c = col0 + nj*8;
            float v0=acc[mi][nj][0], v1=acc[mi][nj][1], v2=acc[mi][nj][2], v3=acc[mi][nj][3];
            if (EPI==0){
                float bc0=b2[c], bc1=b2[c+1];
                v0=gelu_f(v0+bc0); v1=gelu_f(v1+bc1);
                v2=gelu_f(v2+bc0); v3=gelu_f(v3+bc1);
            }
            *(__half2*)(C + (size_t)r*NC + c)     = __floats2half2_rn(v0, v1);
            *(__half2*)(C + (size_t)(r+8)*NC + c) = __floats2half2_rn(v2, v3);
        }
    }
}

/* per-conv prep: xh = half(x); R = x@Wroot + bias; Q = x@b3r.
   conv==0: x = nodes, R -> g_t1 ; conv==1: x = gelu(g_t1) inline, R -> out */
__global__ void k_prep(int conv, const float* __restrict__ x_ext,
                       const float* __restrict__ Wr, const float* __restrict__ bias,
                       const float* __restrict__ b3, float* __restrict__ R_ext){
    __shared__ float xs[L_DIM];
    int n = blockIdx.x, o = threadIdx.x;
    float* R = (conv==0) ? g_t1 : R_ext;
    float xv_in = (conv==0) ? x_ext[n*L_DIM + o] : gelu_f(g_t1[n*L_DIM + o]);
    xs[o] = xv_in;
    __syncthreads();
    g_xh[n*L_DIM + o] = __float2half(xs[o]);
    float r = bias[o], q = 0.f;
    #pragma unroll
    for (int i=0;i<L_DIM;i++){
        float xv = xs[i];
        r += xv*Wr[i*L_DIM + o];
        q += xv*b3[i*L_DIM + o];
    }
    R[n*L_DIM + o] = r;
    g_Q[n*L_DIM + o] = q;
}

/* Tensor-core contraction: per src node n, for each group of 16 edges,
   msg[16,64] = h2[16,256] @ P[n][256,64] via m16n8k16 (8 warps = 8 n-slices),
   then atomicAdd(msg + Q) into dst rows. */
#define PS_PITCH 72
#define HS_PITCH 264
__global__ void __launch_bounds__(256) k_contract(int conv, const int* __restrict__ ei,
                                                  float* __restrict__ out_ext){
    extern __shared__ __align__(16) __half smh[];
    __half* Ps = smh;                       /* 256*72 halfs */
    __half* hs = smh + 256*PS_PITCH;        /* 16*264 halfs */
    float*  Qs = (float*)(hs + 16*HS_PITCH);/* 64 floats */
    float* target = (conv==0) ? g_t1 : out_ext;

    int n = blockIdx.x;
    int beg = g_off[n], end = g_off[n+1];
    if (beg == end) return;
    int t = threadIdx.x, lane = t&31, wn = t>>5;

    /* stage P row (32KB fp16) with pitch-72 rows */
    {
        const uint4* src = (const uint4*)(g_Ph + (size_t)n*P_COLS);
        #pragma unroll
        for (int i=0;i<8;i++){
            int j = t + i*256;
            int k = j>>3, o = (j&7)*8;
            *(uint4*)(Ps + k*PS_PITCH + o) = src[j];
        }
    }
    if (t < 64) Qs[t] = g_Q[n*L_DIM + t];

    for (int gb = beg; gb < end; gb += 16){
        int ne = min(16, end - gb);
        __syncthreads();
        #pragma unroll
        for (int i=0;i<2;i++){
            int j = t + i*256;
            int le = j>>5, c8 = j&31;
            uint4 v;
            if (le < ne){
                int e = g_order[gb+le];
                v = ((const uint4*)(g_h2h + (size_t)e*K_DIM))[c8];
            } else {
                v.x=0u; v.y=0u; v.z=0u; v.w=0u;
            }
            *(uint4*)(hs + le*HS_PITCH + c8*8) = v;
        }
        __syncthreads();

        float acc[4]; acc[0]=0.f; acc[1]=0.f; acc[2]=0.f; acc[3]=0.f;
        #pragma unroll
        for (int ks=0; ks<16; ks++){
            uint32_t af[4];
            ldm_x4(af, hs + (lane&15)*HS_PITCH + ks*16 + (lane>>4)*8);
            uint32_t bf[2];
            ldm_x2_t(bf, Ps + (ks*16 + (lane&15))*PS_PITCH + wn*8);
            mma16816(acc, af, bf);
        }

        int r0 = lane>>2;
        int c0 = wn*8 + (lane&3)*2;
        float q0 = Qs[c0], q1 = Qs[c0+1];
        if (r0 < ne){
            int e = g_order[gb+r0];
            int dst = ei[N_EDGES + e];
            float* tg = target + (size_t)dst*L_DIM + c0;
            atomicAdd(tg,   acc[0]+q0);
            atomicAdd(tg+1, acc[1]+q1);
        }
        if (r0+8 < ne){
            int e = g_order[gb+r0+8];
            int dst = ei[N_EDGES + e];
            float* tg = target + (size_t)dst*L_DIM + c0;
            atomicAdd(tg,   acc[2]+q0);
            atomicAdd(tg+1, acc[3]+q1);
        }
    }
}

extern "C" void kernel_launch(void* const* d_in, const int* in_sizes, int n_in,
                              void* d_out, int out_size){
    const float* nodes = (const float*)d_in[0];
    const int*   ei    = (const int*)  d_in[1];
    const float* ea    = (const float*)d_in[2];
    const float* W1    = (const float*)d_in[3];
    const float* b1    = (const float*)d_in[4];
    const float* W2    = (const float*)d_in[5];
    const float* b2    = (const float*)d_in[6];
    const float* W3    = (const float*)d_in[7];
    const float* b3    = (const float*)d_in[8];
    const float* Wr    = (const float*)d_in[9];
    const float* bias  = (const float*)d_in[10];
    float* out = (float*)d_out;
    (void)in_sizes; (void)n_in; (void)out_size;

    const int SMEM_CONTRACT = (256*PS_PITCH + 16*HS_PITCH)*2 + 64*4 + 16; /* ~45.6 KB */
    cudaFuncSetAttribute(k_contract, cudaFuncAttributeMaxDynamicSharedMemorySize, SMEM_CONTRACT);

    /* sort edges by src */
    k_zero<<<16,256>>>();
    k_hist<<<256,256>>>(ei);
    k_scan<<<1,1024>>>();
    k_scatter<<<256,256>>>(ei);

    /* weight converts (merged) */
    k_wcvt<<<4096,256>>>(W2, W3);

    /* edge MLP (once; reused across both convs) */
    k_mlp1<<<N_EDGES/16,256>>>(ea, W1, b1);
    k_gemm<0,K_DIM,K_DIM><<<dim3(N_EDGES/128, K_DIM/128), 256>>>(b2);

    /* conv 1 */
    k_prep<<<N_NODES,L_DIM>>>(0, nodes, Wr, bias, b3, out);
    k_gemm<1,L_DIM,P_COLS><<<dim3(N_NODES/128, P_COLS/128), 256>>>(b2);
    k_contract<<<N_NODES,256,SMEM_CONTRACT>>>(0, ei, out);

    /* conv 2 (gelu folded into prep) */
    k_prep<<<N_NODES,L_DIM>>>(1, nodes, Wr, bias, b3, out);
    k_gemm<1,L_DIM,P_COLS><<<dim3(N_NODES/128, P_COLS/128), 256>>>(b2);
    k_contract<<<N_NODES,256,SMEM_CONTRACT>>>(1, ei, out);
}

// round 15
// speedup vs baseline: 1.1533x; 1.0569x over previous
/*
 R15 theory.
 Evidence: R14 = 342us; traffic+flop model accounts for ~190us -> ~150us is
 serialization across 14 stream-ordered launches (each with ramp/drain) and
 idle SMs during small kernels.
 Changes (arithmetic bit-identical, rel_err should stay 4.050e-4):
  1. Merge independent kernels into heterogeneous-grid launches:
     - k_misc0  = zero(cnt) + wcvt(W2,W3) + prep(conv0)   [independent inputs]
     - k_scat_mlp1 = scatter + mlp1                        [independent]
     - k_gemm_both = gemm1 (1024 blks) + pgemm1 (4096 blks): these two GEMMs
       are data-independent (edge path vs node path) and now co-run, filling
       the 148 SMs instead of running back to back.
     Launch count 14 -> 9.
  2. prep reworked to 256-thr/4-node blocks (fewer blocks, same math order).
  3. contract: cache dst indices in SMEM during h2 staging (kills 1 extra
     g_order+ei load per edge).
 Side effect: with 9 launches, ncu -s 5 -c 1 now lands on contract1 instead of
 k_scatter, giving real roofline data for the suspected long pole next round.
 Predicted: dur 342 -> ~300-315us, rel_err 4.05e-4 unchanged. If delta is
 smaller, remaining cost is inside contract/pgemm chains -> next round:
 persistent cooperative kernel or repacked pgemm epilogue per new ncu data.
*/
#include <cuda_runtime.h>
#include <cuda_fp16.h>
#include <cstdint>
#include <cstddef>

#define N_NODES 4096
#define N_EDGES 65536
#define L_DIM   64
#define K_DIM   256
#define ED_DIM  6
#define P_COLS  (K_DIM*L_DIM)   /* 16384 */

/* device-global scratch (no runtime allocation allowed) */
__device__ __align__(16) __half g_h1[(size_t)N_EDGES*K_DIM];    /* 32 MB */
__device__ __align__(16) __half g_h2h[(size_t)N_EDGES*K_DIM];   /* 32 MB */
__device__ __align__(16) __half g_W2h[K_DIM*K_DIM];
__device__ __align__(16) __half g_T2h[(size_t)L_DIM*P_COLS];    /* W3 permuted [i][k*64+o] */
__device__ __align__(16) __half g_Ph[(size_t)N_NODES*P_COLS];   /* 134 MB */
__device__ __align__(16) __half g_xh[N_NODES*L_DIM];
__device__ __align__(16) float  g_Q[N_NODES*L_DIM];
__device__ __align__(16) float  g_t1[N_NODES*L_DIM];
__device__ int g_cnt[N_NODES];
__device__ int g_off[N_NODES+1];
__device__ int g_cur[N_NODES];
__device__ int g_order[N_EDGES];

__device__ __forceinline__ float gelu_f(float x){
    return 0.5f*x*(1.0f+erff(x*0.70710678118654752440f));
}

/* mma + cp.async helpers */
__device__ __forceinline__ void ldm_x4(uint32_t* r, const void* p){
    uint32_t a = (uint32_t)__cvta_generic_to_shared(p);
    asm volatile("ldmatrix.sync.aligned.m8n8.x4.shared.b16 {%0,%1,%2,%3},[%4];"
                 : "=r"(r[0]),"=r"(r[1]),"=r"(r[2]),"=r"(r[3]) : "r"(a));
}
__device__ __forceinline__ void ldm_x4_t(uint32_t* r, const void* p){
    uint32_t a = (uint32_t)__cvta_generic_to_shared(p);
    asm volatile("ldmatrix.sync.aligned.m8n8.x4.trans.shared.b16 {%0,%1,%2,%3},[%4];"
                 : "=r"(r[0]),"=r"(r[1]),"=r"(r[2]),"=r"(r[3]) : "r"(a));
}
__device__ __forceinline__ void ldm_x2_t(uint32_t* r, const void* p){
    uint32_t a = (uint32_t)__cvta_generic_to_shared(p);
    asm volatile("ldmatrix.sync.aligned.m8n8.x2.trans.shared.b16 {%0,%1},[%2];"
                 : "=r"(r[0]),"=r"(r[1]) : "r"(a));
}
__device__ __forceinline__ void mma16816(float* d, const uint32_t* a, const uint32_t* b){
    asm volatile("mma.sync.aligned.m16n8k16.row.col.f32.f16.f16.f32 "
                 "{%0,%1,%2,%3},{%4,%5,%6,%7},{%8,%9},{%0,%1,%2,%3};"
                 : "+f"(d[0]),"+f"(d[1]),"+f"(d[2]),"+f"(d[3])
                 : "r"(a[0]),"r"(a[1]),"r"(a[2]),"r"(a[3]),"r"(b[0]),"r"(b[1]));
}
__device__ __forceinline__ void cp16(void* s, const void* g){
    uint32_t a = (uint32_t)__cvta_generic_to_shared(s);
    asm volatile("cp.async.ca.shared.global [%0],[%1],16;" :: "r"(a),"l"(g));
}
__device__ __forceinline__ void cp_commit(){ asm volatile("cp.async.commit_group;"); }
__device__ __forceinline__ void cp_wait0(){ asm volatile("cp.async.wait_group 0;"); }

/* ---- prep body: 4 nodes per 256-thr block ---- */
__device__ __forceinline__ void prep_body(int blk, int conv, const float* x_ext,
                                          const float* Wr, const float* bias,
                                          const float* b3, float* R_ext){
    __shared__ float xs[4][L_DIM];
    int t = threadIdx.x;
    int ln = t >> 6, o = t & 63;
    int n = blk*4 + ln;
    float* R = (conv==0) ? g_t1 : R_ext;
    float xv_in = (conv==0) ? x_ext[n*L_DIM + o] : gelu_f(g_t1[n*L_DIM + o]);
    xs[ln][o] = xv_in;
    __syncthreads();
    g_xh[n*L_DIM + o] = __float2half(xs[ln][o]);
    float r = bias[o], q = 0.f;
    #pragma unroll
    for (int i=0;i<L_DIM;i++){
        float xv = xs[ln][i];
        r += xv*Wr[i*L_DIM + o];
        q += xv*b3[i*L_DIM + o];
    }
    R[n*L_DIM + o] = r;
    g_Q[n*L_DIM + o] = q;
}

/* ---- merged launch 0: zero cnt | weight cvt | prep(conv0) ---- */
#define MISC_ZERO_BLKS  16
#define MISC_WCVT_BLKS  4096
#define MISC_PREP_BLKS  (N_NODES/4)
__global__ void __launch_bounds__(256) k_misc0(const float* __restrict__ W2,
                                               const float* __restrict__ W3,
                                               const float* __restrict__ nodes,
                                               const float* __restrict__ Wr,
                                               const float* __restrict__ bias,
                                               const float* __restrict__ b3){
    int bx = blockIdx.x;
    if (bx < MISC_ZERO_BLKS){
        g_cnt[bx*256 + threadIdx.x] = 0;
    } else if (bx < MISC_ZERO_BLKS + MISC_WCVT_BLKS){
        int idx = (bx - MISC_ZERO_BLKS)*256 + threadIdx.x;
        if (idx < K_DIM*K_DIM) g_W2h[idx] = __float2half(W2[idx]);
        if (idx < K_DIM*L_DIM*L_DIM){
            int k = idx >> 12;
            int i = (idx >> 6) & 63;
            int o = idx & 63;
            g_T2h[(size_t)i*P_COLS + k*L_DIM + o] = __float2half(W3[idx]);
        }
    } else {
        prep_body(bx - MISC_ZERO_BLKS - MISC_WCVT_BLKS, 0, nodes, Wr, bias, b3, (float*)0);
    }
}

__global__ void __launch_bounds__(256) k_prep1(const float* __restrict__ Wr,
                                               const float* __restrict__ bias,
                                               const float* __restrict__ b3,
                                               float* __restrict__ R_ext){
    prep_body(blockIdx.x, 1, (const float*)0, Wr, bias, b3, R_ext);
}

/* ---- sort: hist, scan ---- */
__global__ void k_hist(const int* __restrict__ ei){
    int e = blockIdx.x*blockDim.x + threadIdx.x;
    if (e < N_EDGES) atomicAdd(&g_cnt[ei[e]], 1);
}
__global__ void k_scan(){   /* 1024 threads, 4 elems each */
    int t = threadIdx.x;
    int b = t*4;
    int v0=g_cnt[b], v1=g_cnt[b+1], v2=g_cnt[b+2], v3=g_cnt[b+3];
    int s1=v0+v1, s2=s1+v2, s3=s2+v3;
    int lane=t&31, warp=t>>5;
    int x=s3;
    #pragma unroll
    for(int d=1;d<32;d<<=1){ int y=__shfl_up_sync(0xffffffffu,x,d); if(lane>=d) x+=y; }
    __shared__ int ws[32];
    if(lane==31) ws[warp]=x;
    __syncthreads();
    if(warp==0){
        int y=ws[lane];
        #pragma unroll
        for(int d=1;d<32;d<<=1){ int z=__shfl_up_sync(0xffffffffu,y,d); if(lane>=d) y+=z; }
        ws[lane]=y;
    }
    __syncthreads();
    int wex = (warp==0)?0:ws[warp-1];
    int ex = wex + (x - s3);
    g_off[b]=ex;        g_cur[b]=ex;
    g_off[b+1]=ex+v0;   g_cur[b+1]=ex+v0;
    g_off[b+2]=ex+s1;   g_cur[b+2]=ex+s1;
    g_off[b+3]=ex+s2;   g_cur[b+3]=ex+s2;
    if(t==1023) g_off[N_NODES]=wex+x;
}

/* ---- merged: scatter | mlp1 ---- */
#define SCAT_BLKS 256
__global__ void __launch_bounds__(256) k_scat_mlp1(const int* __restrict__ ei,
                                                   const float* __restrict__ ea,
                                                   const float* __restrict__ W1,
                                                   const float* __restrict__ b1){
    int bx = blockIdx.x;
    if (bx < SCAT_BLKS){
        int e = bx*256 + threadIdx.x;
        int pos = atomicAdd(&g_cur[ei[e]], 1);
        g_order[pos] = e;
        return;
    }
    /* mlp1: 16 edges per block */
    __shared__ float W1s[ED_DIM*K_DIM];
    __shared__ float eas[16][ED_DIM];
    int t = threadIdx.x;
    for (int j=t; j<ED_DIM*K_DIM; j+=256) W1s[j] = W1[j];
    int e0 = (bx - SCAT_BLKS)*16;
    if (t < 16*ED_DIM) eas[t/ED_DIM][t%ED_DIM] = ea[e0*ED_DIM + t];
    float bb = b1[t];
    __syncthreads();
    #pragma unroll
    for (int le=0; le<16; le++){
        float s = bb;
        #pragma unroll
        for (int d=0; d<ED_DIM; d++) s += eas[le][d]*W1s[d*K_DIM + t];
        g_h1[(size_t)(e0+le)*K_DIM + t] = __float2half(gelu_f(s));
    }
}

/* ---- fp16 MMA GEMM body: 128x128 tile, 8 warps, cp.async double buffer ---- */
template<int EPI, int KT, int NC>
__device__ __forceinline__ void gemm_body(int bm, int bn, const float* b2,
                                          __half (*As)[128][40], __half (*Bs)[32][136]){
    const __half* A = (EPI==0) ? (const __half*)g_h1 : (const __half*)g_xh;
    const __half* B = (EPI==0) ? (const __half*)g_W2h : (const __half*)g_T2h;
    __half*       C = (EPI==0) ? g_h2h : g_Ph;
    int t = threadIdx.x, lane = t&31, wid = t>>5;
    int wm = wid & 3, wn = wid >> 2;

    int a_r0 = t>>2,        a_c0 = (t&3)*8;
    int a_r1 = (t+256)>>2,  a_c1 = (t&3)*8;
    int b_r0 = t>>4,        b_c0 = (t&15)*8;
    int b_r1 = (t+256)>>4,  b_c1 = (t&15)*8;

    float acc[2][8][4];
    #pragma unroll
    for (int mi=0;mi<2;mi++)
        #pragma unroll
        for (int nj=0;nj<8;nj++){
            acc[mi][nj][0]=0.f; acc[mi][nj][1]=0.f; acc[mi][nj][2]=0.f; acc[mi][nj][3]=0.f;
        }

    cp16(&As[0][a_r0][a_c0], A + (size_t)(bm*128+a_r0)*KT + a_c0);
    cp16(&As[0][a_r1][a_c1], A + (size_t)(bm*128+a_r1)*KT + a_c1);
    cp16(&Bs[0][b_r0][b_c0], B + (size_t)b_r0*NC + bn*128 + b_c0);
    cp16(&Bs[0][b_r1][b_c1], B + (size_t)b_r1*NC + bn*128 + b_c1);
    cp_commit();

    const int NKT = KT/32;
    for (int kt=0; kt<NKT; kt++){
        cp_wait0();
        __syncthreads();
        if (kt+1 < NKT){
            int st = (kt+1)&1;
            cp16(&As[st][a_r0][a_c0], A + (size_t)(bm*128+a_r0)*KT + (kt+1)*32 + a_c0);
            cp16(&As[st][a_r1][a_c1], A + (size_t)(bm*128+a_r1)*KT + (kt+1)*32 + a_c1);
            cp16(&Bs[st][b_r0][b_c0], B + (size_t)((kt+1)*32+b_r0)*NC + bn*128 + b_c0);
            cp16(&Bs[st][b_r1][b_c1], B + (size_t)((kt+1)*32+b_r1)*NC + bn*128 + b_c1);
            cp_commit();
        }
        int cs = kt&1;
        #pragma unroll
        for (int k16=0;k16<2;k16++){
            uint32_t af[2][4];
            #pragma unroll
            for (int mi=0;mi<2;mi++)
                ldm_x4(af[mi], &As[cs][wm*32 + mi*16 + (lane&15)][k16*16 + (lane>>4)*8]);
            uint32_t bf[8][2];
            #pragma unroll
            for (int np=0;np<4;np++){
                uint32_t r4[4];
                ldm_x4_t(r4, &Bs[cs][k16*16 + ((lane>>3)&1)*8 + (lane&7)]
                               [wn*64 + np*16 + (lane>>4)*8]);
                bf[np*2  ][0]=r4[0]; bf[np*2  ][1]=r4[1];
                bf[np*2+1][0]=r4[2]; bf[np*2+1][1]=r4[3];
            }
            #pragma unroll
            for (int mi=0;mi<2;mi++)
                #pragma unroll
                for (int nj=0;nj<8;nj++)
                    mma16816(acc[mi][nj], af[mi], bf[nj]);
        }
    }
    int row0 = bm*128 + wm*32 + (lane>>2);
    int col0 = bn*128 + wn*64 + (lane&3)*2;
    #pragma unroll
    for (int mi=0;mi<2;mi++){
        #pragma unroll
        for (int nj=0;nj<8;nj++){
            int r = row0 + mi*16, c = col0 + nj*8;
            float v0=acc[mi][nj][0], v1=acc[mi][nj][1], v2=acc[mi][nj][2], v3=acc[mi][nj][3];
            if (EPI==0){
                float bc0=b2[c], bc1=b2[c+1];
                v0=gelu_f(v0+bc0); v1=gelu_f(v1+bc1);
                v2=gelu_f(v2+bc0); v3=gelu_f(v3+bc1);
            }
            *(__half2*)(C + (size_t)r*NC + c)     = __floats2half2_rn(v0, v1);
            *(__half2*)(C + (size_t)(r+8)*NC + c) = __floats2half2_rn(v2, v3);
        }
    }
}

/* gemm1 (1024 blocks) + pgemm1 (4096 blocks) co-scheduled in one launch */
#define G1_BLKS 1024
__global__ void __launch_bounds__(256) k_gemm_both(const float* __restrict__ b2){
    __shared__ __align__(16) __half As[2][128][40];
    __shared__ __align__(16) __half Bs[2][32][136];
    int gb = blockIdx.x;
    if (gb < G1_BLKS){
        gemm_body<0,K_DIM,K_DIM>(gb>>1, gb&1, b2, As, Bs);
    } else {
        int idx = gb - G1_BLKS;
        gemm_body<1,L_DIM,P_COLS>(idx&31, idx>>5, b2, As, Bs);
    }
}
__global__ void __launch_bounds__(256) k_pgemm(const float* __restrict__ b2){
    __shared__ __align__(16) __half As[2][128][40];
    __shared__ __align__(16) __half Bs[2][32][136];
    int idx = blockIdx.x;
    gemm_body<1,L_DIM,P_COLS>(idx&31, idx>>5, b2, As, Bs);
}

/* ---- tensor-core contraction ---- */
#define PS_PITCH 72
#define HS_PITCH 264
__global__ void __launch_bounds__(256) k_contract(int conv, const int* __restrict__ ei,
                                                  float* __restrict__ out_ext){
    extern __shared__ __align__(16) __half smh[];
    __half* Ps = smh;                       /* 256*72 halfs */
    __half* hs = smh + 256*PS_PITCH;        /* 16*264 halfs */
    float*  Qs = (float*)(hs + 16*HS_PITCH);/* 64 floats */
    int*    dsts = (int*)(Qs + 64);         /* 16 ints */
    float* target = (conv==0) ? g_t1 : out_ext;

    int n = blockIdx.x;
    int beg = g_off[n], end = g_off[n+1];
    if (beg == end) return;
    int t = threadIdx.x, lane = t&31, wn = t>>5;

    {
        const uint4* src = (const uint4*)(g_Ph + (size_t)n*P_COLS);
        #pragma unroll
        for (int i=0;i<8;i++){
            int j = t + i*256;
            int k = j>>3, o = (j&7)*8;
            *(uint4*)(Ps + k*PS_PITCH + o) = src[j];
        }
    }
    if (t < 64) Qs[t] = g_Q[n*L_DIM + t];

    for (int gb = beg; gb < end; gb += 16){
        int ne = min(16, end - gb);
        __syncthreads();
        #pragma unroll
        for (int i=0;i<2;i++){
            int j = t + i*256;
            int le = j>>5, c8 = j&31;
            uint4 v;
            if (le < ne){
                int e = g_order[gb+le];
                v = ((const uint4*)(g_h2h + (size_t)e*K_DIM))[c8];
                if (c8 == 0) dsts[le] = ei[N_EDGES + e];
            } else {
                v.x=0u; v.y=0u; v.z=0u; v.w=0u;
            }
            *(uint4*)(hs + le*HS_PITCH + c8*8) = v;
        }
        __syncthreads();

        float acc[4]; acc[0]=0.f; acc[1]=0.f; acc[2]=0.f; acc[3]=0.f;
        #pragma unroll
        for (int ks=0; ks<16; ks++){
            uint32_t af[4];
            ldm_x4(af, hs + (lane&15)*HS_PITCH + ks*16 + (lane>>4)*8);
            uint32_t bf[2];
            ldm_x2_t(bf, Ps + (ks*16 + (lane&15))*PS_PITCH + wn*8);
            mma16816(acc, af, bf);
        }

        int r0 = lane>>2;
        int c0 = wn*8 + (lane&3)*2;
        float q0 = Qs[c0], q1 = Qs[c0+1];
        if (r0 < ne){
            float* tg = target + (size_t)dsts[r0]*L_DIM + c0;
            atomicAdd(tg,   acc[0]+q0);
            atomicAdd(tg+1, acc[1]+q1);
        }
        if (r0+8 < ne){
            float* tg = target + (size_t)dsts[r0+8]*L_DIM + c0;
            atomicAdd(tg,   acc[2]+q0);
            atomicAdd(tg+1, acc[3]+q1);
        }
    }
}

extern "C" void kernel_launch(void* const* d_in, const int* in_sizes, int n_in,
                              void* d_out, int out_size){
    const float* nodes = (const float*)d_in[0];
    const int*   ei    = (const int*)  d_in[1];
    const float* ea    = (const float*)d_in[2];
    const float* W1    = (const float*)d_in[3];
    const float* b1    = (const float*)d_in[4];
    const float* W2    = (const float*)d_in[5];
    const float* b2    = (const float*)d_in[6];
    const float* W3    = (const float*)d_in[7];
    const float* b3    = (const float*)d_in[8];
    const float* Wr    = (const float*)d_in[9];
    const float* bias  = (const float*)d_in[10];
    float* out = (float*)d_out;
    (void)in_sizes; (void)n_in; (void)out_size;

    const int SMEM_CONTRACT = (256*PS_PITCH + 16*HS_PITCH)*2 + 64*4 + 16*4 + 16;
    cudaFuncSetAttribute(k_contract, cudaFuncAttributeMaxDynamicSharedMemorySize, SMEM_CONTRACT);

    /* L0: zero | wcvt | prep(conv0)  — all independent */
    k_misc0<<<MISC_ZERO_BLKS + MISC_WCVT_BLKS + MISC_PREP_BLKS, 256>>>(W2, W3, nodes, Wr, bias, b3);
    /* L1-L2: sort chain */
    k_hist<<<256,256>>>(ei);
    k_scan<<<1,1024>>>();
    /* L3: scatter | mlp1 (independent) */
    k_scat_mlp1<<<SCAT_BLKS + N_EDGES/16, 256>>>(ei, ea, W1, b1);
    /* L4: gemm1 | pgemm1 co-run */
    k_gemm_both<<<G1_BLKS + 4096, 256>>>(b2);
    /* L5: contract1 */
    k_contract<<<N_NODES,256,SMEM_CONTRACT>>>(0, ei, out);
    /* L6: prep conv2 (gelu folded) */
    k_prep1<<<N_NODES/4,256>>>(Wr, bias, b3, out);
    /* L7: pgemm2 */
    k_pgemm<<<4096,256>>>(b2);
    /* L8: contract2 */
    k_contract<<<N_NODES,256,SMEM_CONTRACT>>>(1, ei, out);
}